// round 16
// baseline (speedup 1.0000x reference)
#include <cuda_runtime.h>
#include <cuda_bf16.h>
#include <math.h>

// ---------------- problem constants ----------------
#define BATCH 8192
#define LPOOL 10
#define NTAB  26
#define VROWS 200000
#define DIM   64
#define RDIM  415
#define RPAD  416
#define POOL_TOTAL (NTAB * BATCH / 4)   // 53248 units, 4 bags each

// ---------------- scratch ----------------
__device__ float g_h1[BATCH * 512];
__device__ float g_h2[BATCH * 256];
__device__ float g_h3[BATCH * 64];
__device__ float g_pooled[NTAB * BATCH * DIM];
__device__ float g_R[BATCH * RPAD];
__device__ float g_z1[BATCH * 512];
__device__ float g_z2[BATCH * 256];
__device__ float g_tW1p[512 * RPAD];     // tW1 repacked to aligned stride 416

// ---------------- embedded pool unit (4 bags / 256-thread block) ----------------
__device__ __forceinline__ void pool_unit(
    const float* __restrict__ tables, const int* __restrict__ idx,
    float* __restrict__ pooled, int unit)
{
    const int bag = unit * 4 + (threadIdx.x >> 6);
    const int d   = threadIdx.x & 63;
    const int t = bag >> 13;
    const int b = bag & (BATCH - 1);

    const int* bagIdx = idx + (size_t)t * (BATCH * LPOOL) + (size_t)b * LPOOL;
    const float* tab = tables + (size_t)t * VROWS * DIM;

    float s = 0.f;
#pragma unroll
    for (int l = 0; l < LPOOL; l++) {
        int r = __ldg(bagIdx + l);
        s += __ldg(tab + (size_t)r * DIM + d);
    }
    pooled[(size_t)bag * DIM + d] = s;
}

// ---------------- repack tW1 [512,415] -> [512,416] (zero pad col) ----------------
__global__ __launch_bounds__(256) void repack_w(
    const float* __restrict__ src, float* __restrict__ dst)
{
    int e = blockIdx.x * 256 + threadIdx.x;          // 512*416 = 212992 elems
    if (e >= 512 * RPAD) return;
    int row = e / RPAD, col = e % RPAD;
    dst[e] = (col < RDIM) ? src[(size_t)row * RDIM + col] : 0.f;
}

// ============================================================
// TF32 tensor-core GEMM, cp.async double-buffered.
// ALL global addresses fed to cp16 must be 16B aligned:
// lda/ldw multiples of 4 floats enforced by caller (padded weights).
// cvt.rna applied at fragment load (matches R5 numerics).
// ============================================================
#define GBM 128
#define GBN 64
#define GBK 32
#define SKP 36
#define SM_BYTES (2 * (GBM + GBN) * SKP * 4)

__device__ __forceinline__ void cp16(float* dst, const float* src, int vb) {
    unsigned d = (unsigned)__cvta_generic_to_shared(dst);
    asm volatile("cp.async.cg.shared.global [%0], [%1], 16, %2;"
                 :: "r"(d), "l"(src), "r"(vb));
}

__device__ __forceinline__ unsigned f2tf32(float x) {
    unsigned r;
    asm("cvt.rna.tf32.f32 %0, %1;" : "=r"(r) : "f"(x));
    return r;
}

__device__ __forceinline__ void mma_tf32(float* c, const unsigned* a, const unsigned* b) {
    asm volatile(
        "mma.sync.aligned.m16n8k8.row.col.f32.tf32.tf32.f32 "
        "{%0,%1,%2,%3}, {%4,%5,%6,%7}, {%8,%9}, {%0,%1,%2,%3};"
        : "+f"(c[0]), "+f"(c[1]), "+f"(c[2]), "+f"(c[3])
        : "r"(a[0]), "r"(a[1]), "r"(a[2]), "r"(a[3]), "r"(b[0]), "r"(b[1]));
}

__global__ __launch_bounds__(256) void gemm_tf32(
    const float* __restrict__ A, int lda,
    const float* __restrict__ W, int ldw,
    const float* __restrict__ bias, float* __restrict__ C,
    int N, int Kt, int Kreal, int relu, int nbx, int gemmBlocks,
    const float* __restrict__ tables, const int* __restrict__ lsi,
    float* __restrict__ pooled, int poolStart)
{
    if ((int)blockIdx.x >= gemmBlocks) {
        pool_unit(tables, lsi, pooled, poolStart + (int)blockIdx.x - gemmBlocks);
        return;
    }

    extern __shared__ float sm[];
    float* AsB = sm;                        // [2][GBM][SKP]
    float* WsB = sm + 2 * GBM * SKP;        // [2][GBN][SKP]

    const int tid  = threadIdx.x;
    const int lane = tid & 31;
    const int wid  = tid >> 5;
    const int wm   = wid & 3;
    const int wn   = wid >> 2;
    const int bx   = (int)blockIdx.x % nbx;
    const int by   = (int)blockIdx.x / nbx;
    const int m0   = by * GBM;
    const int n0   = bx * GBN;
    const int qr   = lane >> 2;
    const int qc   = lane & 3;

    float acc[2][4][4];
#pragma unroll
    for (int mt = 0; mt < 2; mt++)
#pragma unroll
        for (int nt = 0; nt < 4; nt++)
#pragma unroll
            for (int e = 0; e < 4; e++) acc[mt][nt][e] = 0.f;

    const int nK = Kt / GBK;

    auto load_stage = [&](int s, int k0) {
        float* As = AsB + s * GBM * SKP;
        float* Ws = WsB + s * GBN * SKP;
#pragma unroll
        for (int i = 0; i < 4; i++) {            // A: 128x32 = 1024 16B chunks
            int c = tid + i * 256;
            int r = c >> 3, ch = c & 7;
            cp16(As + r * SKP + ch * 4,
                 A + (size_t)(m0 + r) * lda + k0 + ch * 4, 16);
        }
#pragma unroll
        for (int i = 0; i < 2; i++) {            // W: 64x32 = 512 chunks, zfill edge
            int c = tid + i * 256;
            int r = c >> 3, ch = c & 7;
            int kk = k0 + ch * 4;
            int vb = (Kreal - kk) * 4;
            vb = vb < 0 ? 0 : (vb > 16 ? 16 : vb);
            cp16(Ws + r * SKP + ch * 4,
                 W + (size_t)(n0 + r) * ldw + kk, vb);
        }
    };

    load_stage(0, 0);
    asm volatile("cp.async.commit_group;");

    for (int kt = 0; kt < nK; kt++) {
        if (kt + 1 < nK) load_stage((kt + 1) & 1, (kt + 1) * GBK);
        asm volatile("cp.async.commit_group;");
        if (kt + 1 < nK) asm volatile("cp.async.wait_group 1;");
        else             asm volatile("cp.async.wait_group 0;");
        __syncthreads();

        const float* As = AsB + (kt & 1) * GBM * SKP;
        const float* Ws = WsB + (kt & 1) * GBN * SKP;

#pragma unroll
        for (int ks = 0; ks < 4; ks++) {
            const int kb = ks * 8;
            unsigned a[2][4], b[4][2];
#pragma unroll
            for (int mt = 0; mt < 2; mt++) {
                int r = wm * 32 + mt * 16 + qr;
                a[mt][0] = f2tf32(As[r * SKP + kb + qc]);
                a[mt][1] = f2tf32(As[(r + 8) * SKP + kb + qc]);
                a[mt][2] = f2tf32(As[r * SKP + kb + qc + 4]);
                a[mt][3] = f2tf32(As[(r + 8) * SKP + kb + qc + 4]);
            }
#pragma unroll
            for (int nt = 0; nt < 4; nt++) {
                int n = wn * 32 + nt * 8 + qr;
                b[nt][0] = f2tf32(Ws[n * SKP + kb + qc]);
                b[nt][1] = f2tf32(Ws[n * SKP + kb + qc + 4]);
            }
#pragma unroll
            for (int mt = 0; mt < 2; mt++)
#pragma unroll
                for (int nt = 0; nt < 4; nt++)
                    mma_tf32(acc[mt][nt], a[mt], b[nt]);
        }
        __syncthreads();
    }

#pragma unroll
    for (int mt = 0; mt < 2; mt++) {
#pragma unroll
        for (int nt = 0; nt < 4; nt++) {
            int row = m0 + wm * 32 + mt * 16 + qr;
            int col = n0 + wn * 32 + nt * 8 + qc * 2;
            float bv0 = bias[col], bv1 = bias[col + 1];
            float v0 = acc[mt][nt][0] + bv0;
            float v1 = acc[mt][nt][1] + bv1;
            float v2 = acc[mt][nt][2] + bv0;
            float v3 = acc[mt][nt][3] + bv1;
            if (relu) {
                v0 = fmaxf(v0, 0.f); v1 = fmaxf(v1, 0.f);
                v2 = fmaxf(v2, 0.f); v3 = fmaxf(v3, 0.f);
            }
            *(float2*)&C[(size_t)row * N + col]       = make_float2(v0, v1);
            *(float2*)&C[(size_t)(row + 8) * N + col] = make_float2(v2, v3);
        }
    }
}

// ---------------- SIMT GEMM for bot1 (K=13) + pool tail ----------------
#define BM 128
#define BN 64
#define BKK 16

__global__ __launch_bounds__(256) void gemm_small_k(
    const float* __restrict__ A, const float* __restrict__ W,
    const float* __restrict__ bias, float* __restrict__ C,
    int N, int K, int nbx, int gemmBlocks,
    const float* __restrict__ tables, const int* __restrict__ lsi,
    float* __restrict__ pooled, int poolStart)
{
    if ((int)blockIdx.x >= gemmBlocks) {
        pool_unit(tables, lsi, pooled, poolStart + (int)blockIdx.x - gemmBlocks);
        return;
    }

    __shared__ float As[BM][BKK + 1];
    __shared__ float Ws[BN][BKK + 1];

    const int tid = threadIdx.x;
    const int tx  = tid & 15;
    const int ty  = tid >> 4;
    const int m0  = ((int)blockIdx.x / nbx) * BM;
    const int n0  = ((int)blockIdx.x % nbx) * BN;

    float acc[8][4];
#pragma unroll
    for (int mi = 0; mi < 8; mi++)
#pragma unroll
        for (int ni = 0; ni < 4; ni++) acc[mi][ni] = 0.f;

    for (int k0 = 0; k0 < K; k0 += BKK) {
#pragma unroll
        for (int e = 0; e < 8; e++) {
            int el = tid + e * 256;
            int r = el >> 4, c = el & 15;
            int kk = k0 + c;
            As[r][c] = (kk < K) ? A[(size_t)(m0 + r) * K + kk] : 0.f;
        }
#pragma unroll
        for (int e = 0; e < 4; e++) {
            int el = tid + e * 256;
            int r = el >> 4, c = el & 15;
            int kk = k0 + c;
            Ws[r][c] = (kk < K) ? W[(size_t)(n0 + r) * K + kk] : 0.f;
        }
        __syncthreads();

#pragma unroll
        for (int k = 0; k < BKK; k++) {
            float a[8], w[4];
#pragma unroll
            for (int mi = 0; mi < 8; mi++) a[mi] = As[ty + 16 * mi][k];
#pragma unroll
            for (int ni = 0; ni < 4; ni++) w[ni] = Ws[tx + 16 * ni][k];
#pragma unroll
            for (int mi = 0; mi < 8; mi++)
#pragma unroll
                for (int ni = 0; ni < 4; ni++)
                    acc[mi][ni] = fmaf(a[mi], w[ni], acc[mi][ni]);
        }
        __syncthreads();
    }

#pragma unroll
    for (int ni = 0; ni < 4; ni++) {
        int n = n0 + tx + 16 * ni;
        float bv = bias[n];
#pragma unroll
        for (int mi = 0; mi < 8; mi++) {
            int m = m0 + ty + 16 * mi;
            float v = fmaxf(acc[mi][ni] + bv, 0.f);
            C[(size_t)m * N + n] = v;
        }
    }
}

// ---------------- dot interaction ----------------
__global__ __launch_bounds__(256) void interact(
    const float* __restrict__ h3, const float* __restrict__ pooled,
    float* __restrict__ R)
{
    const int b = blockIdx.x;
    __shared__ float T[27 * 64];

    for (int e = threadIdx.x; e < 27 * 64; e += 256) {
        int row = e >> 6, d = e & 63;
        T[e] = (row == 0) ? h3[(size_t)b * 64 + d]
                          : pooled[((size_t)(row - 1) * BATCH + b) * 64 + d];
    }
    __syncthreads();

    float* Rb = R + (size_t)b * RPAD;
    if (threadIdx.x < 64) Rb[threadIdx.x] = T[threadIdx.x];
    if (threadIdx.x == 64) Rb[RDIM] = 0.f;

    for (int p = threadIdx.x; p < 351; p += 256) {
        int i = (int)((1.0f + sqrtf(8.0f * (float)p + 1.0f)) * 0.5f);
        while (i * (i - 1) / 2 > p) i--;
        while ((i + 1) * i / 2 <= p) i++;
        int j = p - i * (i - 1) / 2;

        const float4* Ti = (const float4*)(T + i * 64);
        const float4* Tj = (const float4*)(T + j * 64);
        float s = 0.f;
#pragma unroll
        for (int k = 0; k < 16; k++) {
            float4 a = Ti[k], c = Tj[k];
            s += a.x * c.x + a.y * c.y + a.z * c.z + a.w * c.w;
        }
        Rb[64 + p] = s;
    }
}

// ---------------- final layer ----------------
__global__ __launch_bounds__(256) void top3_sigmoid(
    const float* __restrict__ z2, const float* __restrict__ w,
    const float* __restrict__ bias, float* __restrict__ out)
{
    const int warp = (blockIdx.x * blockDim.x + threadIdx.x) >> 5;
    const int lane = threadIdx.x & 31;
    if (warp >= BATCH) return;

    const float* zr = z2 + (size_t)warp * 256;
    float s = 0.f;
#pragma unroll
    for (int k = 0; k < 8; k++)
        s += zr[lane + 32 * k] * w[lane + 32 * k];
#pragma unroll
    for (int off = 16; off; off >>= 1)
        s += __shfl_down_sync(0xffffffffu, s, off);
    if (lane == 0)
        out[warp] = 1.f / (1.f + expf(-(s + bias[0])));
}

// ---------------- launch ----------------
extern "C" void kernel_launch(void* const* d_in, const int* in_sizes, int n_in,
                              void* d_out, int out_size)
{
    const float* x    = (const float*)d_in[0];
    const int*   lS_i = (const int*)d_in[1];   // int32 (JAX x64 disabled)
    const float* emb = (const float*)d_in[3];
    const float* bW1 = (const float*)d_in[4],  *bb1 = (const float*)d_in[5];
    const float* bW2 = (const float*)d_in[6],  *bb2 = (const float*)d_in[7];
    const float* bW3 = (const float*)d_in[8],  *bb3 = (const float*)d_in[9];
    const float* tW1 = (const float*)d_in[10], *tb1 = (const float*)d_in[11];
    const float* tW2 = (const float*)d_in[12], *tb2 = (const float*)d_in[13];
    const float* tW3 = (const float*)d_in[14], *tb3 = (const float*)d_in[15];
    float* out = (float*)d_out;

    float *h1, *h2, *h3, *pooled, *R, *z1, *z2, *tW1p;
    cudaGetSymbolAddress((void**)&h1, g_h1);
    cudaGetSymbolAddress((void**)&h2, g_h2);
    cudaGetSymbolAddress((void**)&h3, g_h3);
    cudaGetSymbolAddress((void**)&pooled, g_pooled);
    cudaGetSymbolAddress((void**)&R, g_R);
    cudaGetSymbolAddress((void**)&z1, g_z1);
    cudaGetSymbolAddress((void**)&z2, g_z2);
    cudaGetSymbolAddress((void**)&tW1p, g_tW1p);

    cudaFuncSetAttribute(gemm_tf32, cudaFuncAttributeMaxDynamicSharedMemorySize, SM_BYTES);

    // repack tW1 to aligned stride (cp.async needs 16B-aligned rows; 415 is not)
    repack_w<<<(512 * RPAD + 255) / 256, 256>>>(tW1, tW1p);

    // pool slices distributed across bottom kernels (sum = POOL_TOTAL)
    const int P1 = 16384, P2 = 20864, P3 = POOL_TOTAL - P1 - P2;

    // bot1 (K=13, SIMT) + pool slice
    {
        int nbx = 512 / BN, gb = nbx * (BATCH / BM);   // 512
        gemm_small_k<<<gb + P1, 256>>>(x, bW1, bb1, h1, 512, 13,
                                       nbx, gb, emb, lS_i, pooled, 0);
    }
    // bot2 (512->256) + pool slice
    {
        int nbx = 256 / GBN, gb = nbx * (BATCH / GBM); // 256
        gemm_tf32<<<gb + P2, 256, SM_BYTES>>>(h1, 512, bW2, 512, bb2, h2,
                                              256, 512, 512, 1, nbx, gb,
                                              emb, lS_i, pooled, P1);
    }
    // bot3 (256->64) + pool slice
    {
        int nbx = 64 / GBN, gb = nbx * (BATCH / GBM);  // 64
        gemm_tf32<<<gb + P3, 256, SM_BYTES>>>(h2, 256, bW3, 256, bb3, h3,
                                              64, 256, 256, 1, nbx, gb,
                                              emb, lS_i, pooled, P1 + P2);
    }

    interact<<<BATCH, 256>>>(h3, pooled, R);

    // top MLP (tW1p: aligned stride RPAD, pad col zero => Kreal = RPAD)
    {
        int nbx = 512 / GBN, gb = nbx * (BATCH / GBM); // 512
        gemm_tf32<<<gb, 256, SM_BYTES>>>(R, RPAD, tW1p, RPAD, tb1, z1,
                                         512, RPAD, RPAD, 1, nbx, gb,
                                         nullptr, nullptr, nullptr, 0);
    }
    {
        int nbx = 256 / GBN, gb = nbx * (BATCH / GBM); // 256
        gemm_tf32<<<gb, 256, SM_BYTES>>>(z1, 512, tW2, 512, tb2, z2,
                                         256, 512, 512, 1, nbx, gb,
                                         nullptr, nullptr, nullptr, 0);
    }
    top3_sigmoid<<<BATCH / 8, 256>>>(z2, tW3, tb3, out);
}

// round 17
// speedup vs baseline: 1.2280x; 1.2280x over previous
#include <cuda_runtime.h>
#include <cuda_bf16.h>
#include <math.h>

// ---------------- problem constants ----------------
#define BATCH 8192
#define LPOOL 10
#define NTAB  26
#define VROWS 200000
#define DIM   64
#define RDIM  415
#define RPAD  416

// ---------------- scratch ----------------
__device__ float g_h1[BATCH * 512];
__device__ float g_h2[BATCH * 256];
__device__ float g_h3[BATCH * 64];
__device__ float g_pooled[NTAB * BATCH * DIM];
__device__ float g_R[BATCH * RPAD];
__device__ float g_z1[BATCH * 512];
__device__ float g_z2[BATCH * 256];
__device__ float g_tW1p[512 * RPAD];     // tW1 repacked to aligned stride 416

// ---------------- embedding pool: float4 gathers, 16 threads/bag ----------------
// 256 threads = 16 bags/block; thread j of a bag owns float4 #j of the 64-dim row.
// 10 independent LDG.128 per thread -> deep MLP, low regs -> full occupancy.
__global__ __launch_bounds__(256) void pool_f4(
    const float* __restrict__ tables, const int* __restrict__ idx,
    float* __restrict__ pooled)
{
    const int bag  = blockIdx.x * 16 + (threadIdx.x >> 4);   // t*BATCH + b
    const int j    = threadIdx.x & 15;                       // float4 slot
    const int t    = bag >> 13;
    const int b    = bag & (BATCH - 1);

    const int* bagIdx = idx + (size_t)t * (BATCH * LPOOL) + (size_t)b * LPOOL;
    const float4* tab = (const float4*)(tables + (size_t)t * VROWS * DIM);

    int r0 = __ldg(bagIdx + 0), r1 = __ldg(bagIdx + 1);
    int r2 = __ldg(bagIdx + 2), r3 = __ldg(bagIdx + 3);
    int r4 = __ldg(bagIdx + 4), r5 = __ldg(bagIdx + 5);
    int r6 = __ldg(bagIdx + 6), r7 = __ldg(bagIdx + 7);
    int r8 = __ldg(bagIdx + 8), r9 = __ldg(bagIdx + 9);

    float4 s = make_float4(0.f, 0.f, 0.f, 0.f);
    float4 v;
#define ACC(rr) v = __ldg(tab + (size_t)(rr) * 16 + j); \
    s.x += v.x; s.y += v.y; s.z += v.z; s.w += v.w;
    ACC(r0) ACC(r1) ACC(r2) ACC(r3) ACC(r4)
    ACC(r5) ACC(r6) ACC(r7) ACC(r8) ACC(r9)
#undef ACC

    ((float4*)(pooled + (size_t)bag * DIM))[j] = s;
}

// ---------------- repack tW1 [512,415] -> [512,416] (zero pad col) ----------------
__global__ __launch_bounds__(256) void repack_w(
    const float* __restrict__ src, float* __restrict__ dst)
{
    int e = blockIdx.x * 256 + threadIdx.x;
    if (e >= 512 * RPAD) return;
    int row = e / RPAD, col = e % RPAD;
    dst[e] = (col < RDIM) ? src[(size_t)row * RDIM + col] : 0.f;
}

// ============================================================
// TF32 tensor-core GEMM, cp.async double-buffered.
// All cp16 global addresses 16B-aligned (lda/ldw % 4 == 0, by caller).
// cvt.rna at fragment load (R5-identical numerics).
// ============================================================
#define GBM 128
#define GBN 64
#define GBK 32
#define SKP 36
#define SM_BYTES (2 * (GBM + GBN) * SKP * 4)

__device__ __forceinline__ void cp16(float* dst, const float* src, int vb) {
    unsigned d = (unsigned)__cvta_generic_to_shared(dst);
    asm volatile("cp.async.cg.shared.global [%0], [%1], 16, %2;"
                 :: "r"(d), "l"(src), "r"(vb));
}

__device__ __forceinline__ unsigned f2tf32(float x) {
    unsigned r;
    asm("cvt.rna.tf32.f32 %0, %1;" : "=r"(r) : "f"(x));
    return r;
}

__device__ __forceinline__ void mma_tf32(float* c, const unsigned* a, const unsigned* b) {
    asm volatile(
        "mma.sync.aligned.m16n8k8.row.col.f32.tf32.tf32.f32 "
        "{%0,%1,%2,%3}, {%4,%5,%6,%7}, {%8,%9}, {%0,%1,%2,%3};"
        : "+f"(c[0]), "+f"(c[1]), "+f"(c[2]), "+f"(c[3])
        : "r"(a[0]), "r"(a[1]), "r"(a[2]), "r"(a[3]), "r"(b[0]), "r"(b[1]));
}

__global__ __launch_bounds__(256) void gemm_tf32(
    const float* __restrict__ A, int lda,
    const float* __restrict__ W, int ldw,
    const float* __restrict__ bias, float* __restrict__ C,
    int N, int Kt, int Kreal, int relu, int nbx)
{
    extern __shared__ float sm[];
    float* AsB = sm;                        // [2][GBM][SKP]
    float* WsB = sm + 2 * GBM * SKP;        // [2][GBN][SKP]

    const int tid  = threadIdx.x;
    const int lane = tid & 31;
    const int wid  = tid >> 5;
    const int wm   = wid & 3;
    const int wn   = wid >> 2;
    const int m0   = ((int)blockIdx.x / nbx) * GBM;
    const int n0   = ((int)blockIdx.x % nbx) * GBN;
    const int qr   = lane >> 2;
    const int qc   = lane & 3;

    float acc[2][4][4];
#pragma unroll
    for (int mt = 0; mt < 2; mt++)
#pragma unroll
        for (int nt = 0; nt < 4; nt++)
#pragma unroll
            for (int e = 0; e < 4; e++) acc[mt][nt][e] = 0.f;

    const int nK = Kt / GBK;

    auto load_stage = [&](int s, int k0) {
        float* As = AsB + s * GBM * SKP;
        float* Ws = WsB + s * GBN * SKP;
#pragma unroll
        for (int i = 0; i < 4; i++) {            // A: 128x32 = 1024 16B chunks
            int c = tid + i * 256;
            int r = c >> 3, ch = c & 7;
            cp16(As + r * SKP + ch * 4,
                 A + (size_t)(m0 + r) * lda + k0 + ch * 4, 16);
        }
#pragma unroll
        for (int i = 0; i < 2; i++) {            // W: 64x32 = 512 chunks, zfill edge
            int c = tid + i * 256;
            int r = c >> 3, ch = c & 7;
            int kk = k0 + ch * 4;
            int vb = (Kreal - kk) * 4;
            vb = vb < 0 ? 0 : (vb > 16 ? 16 : vb);
            cp16(Ws + r * SKP + ch * 4,
                 W + (size_t)(n0 + r) * ldw + kk, vb);
        }
    };

    load_stage(0, 0);
    asm volatile("cp.async.commit_group;");

    for (int kt = 0; kt < nK; kt++) {
        if (kt + 1 < nK) load_stage((kt + 1) & 1, (kt + 1) * GBK);
        asm volatile("cp.async.commit_group;");
        if (kt + 1 < nK) asm volatile("cp.async.wait_group 1;");
        else             asm volatile("cp.async.wait_group 0;");
        __syncthreads();

        const float* As = AsB + (kt & 1) * GBM * SKP;
        const float* Ws = WsB + (kt & 1) * GBN * SKP;

#pragma unroll
        for (int ks = 0; ks < 4; ks++) {
            const int kb = ks * 8;
            unsigned a[2][4], b[4][2];
#pragma unroll
            for (int mt = 0; mt < 2; mt++) {
                int r = wm * 32 + mt * 16 + qr;
                a[mt][0] = f2tf32(As[r * SKP + kb + qc]);
                a[mt][1] = f2tf32(As[(r + 8) * SKP + kb + qc]);
                a[mt][2] = f2tf32(As[r * SKP + kb + qc + 4]);
                a[mt][3] = f2tf32(As[(r + 8) * SKP + kb + qc + 4]);
            }
#pragma unroll
            for (int nt = 0; nt < 4; nt++) {
                int n = wn * 32 + nt * 8 + qr;
                b[nt][0] = f2tf32(Ws[n * SKP + kb + qc]);
                b[nt][1] = f2tf32(Ws[n * SKP + kb + qc + 4]);
            }
#pragma unroll
            for (int mt = 0; mt < 2; mt++)
#pragma unroll
                for (int nt = 0; nt < 4; nt++)
                    mma_tf32(acc[mt][nt], a[mt], b[nt]);
        }
        __syncthreads();
    }

#pragma unroll
    for (int mt = 0; mt < 2; mt++) {
#pragma unroll
        for (int nt = 0; nt < 4; nt++) {
            int row = m0 + wm * 32 + mt * 16 + qr;
            int col = n0 + wn * 32 + nt * 8 + qc * 2;
            float bv0 = bias[col], bv1 = bias[col + 1];
            float v0 = acc[mt][nt][0] + bv0;
            float v1 = acc[mt][nt][1] + bv1;
            float v2 = acc[mt][nt][2] + bv0;
            float v3 = acc[mt][nt][3] + bv1;
            if (relu) {
                v0 = fmaxf(v0, 0.f); v1 = fmaxf(v1, 0.f);
                v2 = fmaxf(v2, 0.f); v3 = fmaxf(v3, 0.f);
            }
            *(float2*)&C[(size_t)row * N + col]       = make_float2(v0, v1);
            *(float2*)&C[(size_t)(row + 8) * N + col] = make_float2(v2, v3);
        }
    }
}

// ---------------- SIMT GEMM for bot1 (K=13) ----------------
#define BM 128
#define BN 64
#define BKK 16

__global__ __launch_bounds__(256) void gemm_small_k(
    const float* __restrict__ A, const float* __restrict__ W,
    const float* __restrict__ bias, float* __restrict__ C,
    int N, int K, int nbx)
{
    __shared__ float As[BM][BKK + 1];
    __shared__ float Ws[BN][BKK + 1];

    const int tid = threadIdx.x;
    const int tx  = tid & 15;
    const int ty  = tid >> 4;
    const int m0  = ((int)blockIdx.x / nbx) * BM;
    const int n0  = ((int)blockIdx.x % nbx) * BN;

    float acc[8][4];
#pragma unroll
    for (int mi = 0; mi < 8; mi++)
#pragma unroll
        for (int ni = 0; ni < 4; ni++) acc[mi][ni] = 0.f;

    for (int k0 = 0; k0 < K; k0 += BKK) {
#pragma unroll
        for (int e = 0; e < 8; e++) {
            int el = tid + e * 256;
            int r = el >> 4, c = el & 15;
            int kk = k0 + c;
            As[r][c] = (kk < K) ? A[(size_t)(m0 + r) * K + kk] : 0.f;
        }
#pragma unroll
        for (int e = 0; e < 4; e++) {
            int el = tid + e * 256;
            int r = el >> 4, c = el & 15;
            int kk = k0 + c;
            Ws[r][c] = (kk < K) ? W[(size_t)(n0 + r) * K + kk] : 0.f;
        }
        __syncthreads();

#pragma unroll
        for (int k = 0; k < BKK; k++) {
            float a[8], w[4];
#pragma unroll
            for (int mi = 0; mi < 8; mi++) a[mi] = As[ty + 16 * mi][k];
#pragma unroll
            for (int ni = 0; ni < 4; ni++) w[ni] = Ws[tx + 16 * ni][k];
#pragma unroll
            for (int mi = 0; mi < 8; mi++)
#pragma unroll
                for (int ni = 0; ni < 4; ni++)
                    acc[mi][ni] = fmaf(a[mi], w[ni], acc[mi][ni]);
        }
        __syncthreads();
    }

#pragma unroll
    for (int ni = 0; ni < 4; ni++) {
        int n = n0 + tx + 16 * ni;
        float bv = bias[n];
#pragma unroll
        for (int mi = 0; mi < 8; mi++) {
            int m = m0 + ty + 16 * mi;
            float v = fmaxf(acc[mi][ni] + bv, 0.f);
            C[(size_t)m * N + n] = v;
        }
    }
}

// ---------------- dot interaction ----------------
__global__ __launch_bounds__(256) void interact(
    const float* __restrict__ h3, const float* __restrict__ pooled,
    float* __restrict__ R)
{
    const int b = blockIdx.x;
    __shared__ float T[27 * 64];

    for (int e = threadIdx.x; e < 27 * 64; e += 256) {
        int row = e >> 6, d = e & 63;
        T[e] = (row == 0) ? h3[(size_t)b * 64 + d]
                          : pooled[((size_t)(row - 1) * BATCH + b) * 64 + d];
    }
    __syncthreads();

    float* Rb = R + (size_t)b * RPAD;
    if (threadIdx.x < 64) Rb[threadIdx.x] = T[threadIdx.x];
    if (threadIdx.x == 64) Rb[RDIM] = 0.f;

    for (int p = threadIdx.x; p < 351; p += 256) {
        int i = (int)((1.0f + sqrtf(8.0f * (float)p + 1.0f)) * 0.5f);
        while (i * (i - 1) / 2 > p) i--;
        while ((i + 1) * i / 2 <= p) i++;
        int j = p - i * (i - 1) / 2;

        const float4* Ti = (const float4*)(T + i * 64);
        const float4* Tj = (const float4*)(T + j * 64);
        float s = 0.f;
#pragma unroll
        for (int k = 0; k < 16; k++) {
            float4 a = Ti[k], c = Tj[k];
            s += a.x * c.x + a.y * c.y + a.z * c.z + a.w * c.w;
        }
        Rb[64 + p] = s;
    }
}

// ---------------- final layer ----------------
__global__ __launch_bounds__(256) void top3_sigmoid(
    const float* __restrict__ z2, const float* __restrict__ w,
    const float* __restrict__ bias, float* __restrict__ out)
{
    const int warp = (blockIdx.x * blockDim.x + threadIdx.x) >> 5;
    const int lane = threadIdx.x & 31;
    if (warp >= BATCH) return;

    const float* zr = z2 + (size_t)warp * 256;
    float s = 0.f;
#pragma unroll
    for (int k = 0; k < 8; k++)
        s += zr[lane + 32 * k] * w[lane + 32 * k];
#pragma unroll
    for (int off = 16; off; off >>= 1)
        s += __shfl_down_sync(0xffffffffu, s, off);
    if (lane == 0)
        out[warp] = 1.f / (1.f + expf(-(s + bias[0])));
}

// ---------------- launch ----------------
extern "C" void kernel_launch(void* const* d_in, const int* in_sizes, int n_in,
                              void* d_out, int out_size)
{
    const float* x    = (const float*)d_in[0];
    const int*   lS_i = (const int*)d_in[1];   // int32 (JAX x64 disabled)
    const float* emb = (const float*)d_in[3];
    const float* bW1 = (const float*)d_in[4],  *bb1 = (const float*)d_in[5];
    const float* bW2 = (const float*)d_in[6],  *bb2 = (const float*)d_in[7];
    const float* bW3 = (const float*)d_in[8],  *bb3 = (const float*)d_in[9];
    const float* tW1 = (const float*)d_in[10], *tb1 = (const float*)d_in[11];
    const float* tW2 = (const float*)d_in[12], *tb2 = (const float*)d_in[13];
    const float* tW3 = (const float*)d_in[14], *tb3 = (const float*)d_in[15];
    float* out = (float*)d_out;

    float *h1, *h2, *h3, *pooled, *R, *z1, *z2, *tW1p;
    cudaGetSymbolAddress((void**)&h1, g_h1);
    cudaGetSymbolAddress((void**)&h2, g_h2);
    cudaGetSymbolAddress((void**)&h3, g_h3);
    cudaGetSymbolAddress((void**)&pooled, g_pooled);
    cudaGetSymbolAddress((void**)&R, g_R);
    cudaGetSymbolAddress((void**)&z1, g_z1);
    cudaGetSymbolAddress((void**)&z2, g_z2);
    cudaGetSymbolAddress((void**)&tW1p, g_tW1p);

    cudaFuncSetAttribute(gemm_tf32, cudaFuncAttributeMaxDynamicSharedMemorySize, SM_BYTES);

    // independent preludes
    repack_w<<<(512 * RPAD + 255) / 256, 256>>>(tW1, tW1p);
    pool_f4<<<NTAB * BATCH / 16, 256>>>(emb, lS_i, pooled);

    // bottom MLP
    gemm_small_k<<<(512 / BN) * (BATCH / BM), 256>>>(x, bW1, bb1, h1, 512, 13, 512 / BN);
    gemm_tf32<<<(256 / GBN) * (BATCH / GBM), 256, SM_BYTES>>>(
        h1, 512, bW2, 512, bb2, h2, 256, 512, 512, 1, 256 / GBN);
    gemm_tf32<<<(64 / GBN) * (BATCH / GBM), 256, SM_BYTES>>>(
        h2, 256, bW3, 256, bb3, h3, 64, 256, 256, 1, 64 / GBN);

    // interaction
    interact<<<BATCH, 256>>>(h3, pooled, R);

    // top MLP (tW1p: aligned stride RPAD, pad col zero => Kreal = RPAD)
    gemm_tf32<<<(512 / GBN) * (BATCH / GBM), 256, SM_BYTES>>>(
        R, RPAD, tW1p, RPAD, tb1, z1, 512, RPAD, RPAD, 1, 512 / GBN);
    gemm_tf32<<<(256 / GBN) * (BATCH / GBM), 256, SM_BYTES>>>(
        z1, 512, tW2, 512, tb2, z2, 256, 512, 512, 1, 256 / GBN);
    top3_sigmoid<<<BATCH / 8, 256>>>(z2, tW3, tb3, out);
}